// round 11
// baseline (speedup 1.0000x reference)
#include <cuda_runtime.h>
#include <cuda_bf16.h>

#define BB 2048
#define TT 128
#define NN 64
#define HH 128
#define THR 256   // threads per CTA (8 warps)
#define GRID 444  // 3 CTAs per SM
#define NFULL 272 // CTAs with 5 batches; remaining 172 have 4
#define HCP 264   // hc row stride (floats): [b][0:128)=h, [128:256)=c

typedef unsigned long long ull;

// ---------------- device scratch (allocation-free: __device__ globals) -------
__device__ __align__(16) __nv_bfloat16 g_prex_bf[(size_t)BB * NN * HH]; // [b][n][kq]
__device__ __align__(16) uint2 g_WhsP[128 * 64];   // [jp][kp]: {bf16x2(j0;k0,k1), bf16x2(j1;k0,k1)}
__device__ __align__(16) float g_W1xT[TT * HH];    // [t][k]
__device__ __align__(16) float4 g_WhhJ[64 * 256];  // [jp][tid]: {Wg0j0,Wg0j1,Wg1j0,Wg1j1}
__device__ __align__(16) float4 g_WihJ[32 * 256];  // [np][tid]
__device__ __align__(16) float2 g_bJ[256];         // [tid]: (bias_g0, bias_g1)

__device__ __forceinline__ ull pk2(float a, float b) {
    ull r; asm("mov.b64 %0,{%1,%2};" : "=l"(r) : "f"(a), "f"(b)); return r;
}
__device__ __forceinline__ void fma2(ull& d, ull a, ull b) {
    asm("fma.rn.f32x2 %0, %1, %2, %0;" : "+l"(d) : "l"(a), "l"(b));
}
__device__ __forceinline__ float2 up2(ull v) {
    float2 r; asm("mov.b64 {%0,%1},%2;" : "=f"(r.x), "=f"(r.y) : "l"(v)); return r;
}
// bf16x2 word -> packed f32x2 (low bf16 -> low f32)
__device__ __forceinline__ ull expw(unsigned wd) {
    unsigned lo = wd << 16, hi = wd & 0xFFFF0000u;
    ull r; asm("mov.b64 %0,{%1,%2};" : "=l"(r) : "r"(lo), "r"(hi)); return r;
}
__device__ __forceinline__ float tanh_fast(float x) {
    float y; asm("tanh.approx.f32 %0, %1;" : "=f"(y) : "f"(x)); return y;
}
__device__ __forceinline__ float sigmoid_f(float x) {
    return 1.0f / (1.0f + __expf(-x));
}
__device__ __forceinline__ void fma4(float4& a, float s, const float4 w) {
    a.x = fmaf(s, w.x, a.x); a.y = fmaf(s, w.y, a.y);
    a.z = fmaf(s, w.z, a.z); a.w = fmaf(s, w.w, a.w);
}
__device__ __forceinline__ unsigned b2u(__nv_bfloat162 v) {
    unsigned r; *(__nv_bfloat162*)&r = v; return r;
}

// ---------------- kernel 0: weight layout prep --------------------------------
__global__ void prep_kernel(const float* __restrict__ W_attn1,
                            const float* __restrict__ W_ih,
                            const float* __restrict__ W_hh,
                            const float* __restrict__ b_ih,
                            const float* __restrict__ b_hh)
{
    int tid = blockIdx.x * blockDim.x + threadIdx.x;
    int nt  = gridDim.x * blockDim.x;
    // attention weights bf16, j-pair x k-pair: W^T[j][k] = W_attn1[k*384 + j]
    for (int i = tid; i < 128 * 64; i += nt) {
        int jp = i >> 6, kp = i & 63;
        int j0 = jp * 2, j1 = j0 + 1, k0 = kp * 2, k1 = k0 + 1;
        uint2 v;
        v.x = b2u(__floats2bfloat162_rn(W_attn1[k0*384 + j0], W_attn1[k1*384 + j0]));
        v.y = b2u(__floats2bfloat162_rn(W_attn1[k0*384 + j1], W_attn1[k1*384 + j1]));
        g_WhsP[i] = v;
    }
    for (int i = tid; i < TT * HH; i += nt) {
        int t = i >> 7, k = i & 127;
        g_W1xT[i] = W_attn1[k * 384 + 256 + t];
    }
    // gate weights, j-pair interleaved per thread (q = tt>>1, gates 2gp,2gp+1)
    for (int i = tid; i < 64 * 256; i += nt) {
        int jp = i >> 8, tt = i & 255;
        int q = tt >> 1, gp = tt & 1, g0 = gp * 2, g1 = g0 + 1;
        int j0 = jp * 2, j1 = j0 + 1;
        float4 v;
        v.x = W_hh[(g0 * HH + q) * HH + j0];
        v.y = W_hh[(g0 * HH + q) * HH + j1];
        v.z = W_hh[(g1 * HH + q) * HH + j0];
        v.w = W_hh[(g1 * HH + q) * HH + j1];
        g_WhhJ[i] = v;
    }
    for (int i = tid; i < 32 * 256; i += nt) {
        int np = i >> 8, tt = i & 255;
        int q = tt >> 1, gp = tt & 1, g0 = gp * 2, g1 = g0 + 1;
        int n0 = np * 2, n1 = n0 + 1;
        float4 v;
        v.x = W_ih[(g0 * HH + q) * NN + n0];
        v.y = W_ih[(g0 * HH + q) * NN + n1];
        v.z = W_ih[(g1 * HH + q) * NN + n0];
        v.w = W_ih[(g1 * HH + q) * NN + n1];
        g_WihJ[i] = v;
    }
    for (int i = tid; i < 256; i += nt) {
        int q = i >> 1, gp = i & 1, g0 = gp * 2, g1 = g0 + 1;
        float2 v;
        v.x = b_ih[g0 * HH + q] + b_hh[g0 * HH + q];
        v.y = b_ih[g1 * HH + q] + b_hh[g1 * HH + q];
        g_bJ[i] = v;
    }
}

// ---------------- kernel 1: pre_x (bf16 out) ----------------------------------
__global__ __launch_bounds__(256) void prex_kernel(const float* __restrict__ X,
                                                   const float* __restrict__ b_attn1)
{
    __shared__ float sX[TT * NN];
    int b = blockIdx.x;
    int tid = threadIdx.x;
    const float* Xb = X + (size_t)b * TT * NN;
    for (int i = tid; i < TT * NN; i += 256) sX[i] = Xb[i];
    __syncthreads();

    const float4* W4  = (const float4*)g_W1xT;
    const float4* b14 = (const float4*)b_attn1;
    uint2* out2 = (uint2*)(g_prex_bf + (size_t)b * NN * HH);

    for (int qi = tid; qi < NN * 32; qi += 256) {
        int n = qi >> 5, kq = qi & 31;
        float4 acc = b14[kq];
        #pragma unroll 4
        for (int t = 0; t < TT; ++t) {
            float x = sX[t * NN + n];
            fma4(acc, x, W4[t * 32 + kq]);
        }
        uint2 st;
        st.x = b2u(__floats2bfloat162_rn(acc.x, acc.y));
        st.y = b2u(__floats2bfloat162_rn(acc.z, acc.w));
        out2[n * 32 + kq] = st;
    }
}

// dummy: shifts launch numbering so ncu (-s 5 -c 1) lands on rnn_kernel
__global__ void dummy_kernel() {}

// ---------------- kernel 2: the recurrence ------------------------------------
// smem (floats):
//   hc    [0,1320)       5 x HCP, h then c
//   hcdup [1320,4392)    ull[256*6]: (v,v) pairs, j<128 h, j>=128 c, slot=batch
//   sUp   [4392,6952)    ull[4*5*64]: u partials [jq][b][kp]
//   sE    [6952,7272)    [b][n]
//   sXT   [7272,7592)    [b][n]
#define SMEM_FLOATS 7592

__global__ __launch_bounds__(THR, 3) void rnn_kernel(
    const float* __restrict__ X,
    const float* __restrict__ w_attn2,
    const float* __restrict__ b_attn2,
    float* __restrict__ out)
{
    extern __shared__ float smem[];
    float* hc    = smem;
    ull*   hcdup = (ull*)(smem + 1320);
    ull*   sUp   = (ull*)(smem + 4392);
    float* sE    = smem + 6952;
    float* sXT   = smem + 7272;

    int tid = threadIdx.x;
    int l = tid & 31;
    int w = tid >> 5;                      // warp 0..7
    int cta = blockIdx.x;
    int cnt = (cta < NFULL) ? 5 : 4;
    size_t b0 = (cta < NFULL) ? (size_t)cta * 5
                              : (size_t)(NFULL * 5 + (cta - NFULL) * 4);

    for (int i = tid; i < SMEM_FLOATS; i += THR) smem[i] = 0.0f;

    float b2 = b_attn2[0];
    float4 w2v = ((const float4*)w_attn2)[l];   // k-quad l

    // (a) mapping: thread owns k-pair kp, j-quarter jq (32 j-pairs)
    int kp = tid & 63, jq = tid >> 6;
    const uint2* Wp = g_WhsP + (jq * 32) * 64 + kp;

    // (d)/(e) mapping
    int qe = tid >> 1, gp = tid & 1;
    float2 bj = g_bJ[tid];
    const ulonglong2* Wh = (const ulonglong2*)g_WhhJ + tid;
    const ulonglong2* Wi = (const ulonglong2*)g_WihJ + tid;

    // per-batch pre_x pointers (clamped for tail CTAs)
    const uint2* prB[5];
    #pragma unroll
    for (int b = 0; b < 5; ++b) {
        int bb = (b < cnt) ? b : (cnt - 1);
        prB[b] = (const uint2*)g_prex_bf + (size_t)(b0 + bb) * 2048;
    }

    __syncthreads();

    for (int t = 0; t < TT; ++t) {
        // ---- (a) u-partials: acc over this thread's 64-j quarter, k-pair kp
        {
            ull acc0 = 0, acc1 = 0, acc2 = 0, acc3 = 0, acc4 = 0;
            uint2 wv = Wp[0];
            #pragma unroll 4
            for (int jl = 0; jl < 32; ++jl) {
                uint2 nx = Wp[((jl + 1) & 31) * 64];
                int j0 = (jq * 32 + jl) * 2;
                const ull* hd0 = hcdup + j0 * 6;
                ull w0 = expw(wv.x), w1 = expw(wv.y);
                ulonglong2 ha = *(const ulonglong2*)hd0;
                ulonglong2 hb = *(const ulonglong2*)(hd0 + 2);
                ull h4 = hd0[4];
                fma2(acc0, ha.x, w0); fma2(acc1, ha.y, w0);
                fma2(acc2, hb.x, w0); fma2(acc3, hb.y, w0);
                fma2(acc4, h4, w0);
                ulonglong2 ga = *(const ulonglong2*)(hd0 + 6);
                ulonglong2 gb = *(const ulonglong2*)(hd0 + 8);
                ull g4 = hd0[10];
                fma2(acc0, ga.x, w1); fma2(acc1, ga.y, w1);
                fma2(acc2, gb.x, w1); fma2(acc3, gb.y, w1);
                fma2(acc4, g4, w1);
                wv = nx;
            }
            sUp[(jq * 5 + 0) * 64 + kp] = acc0;
            sUp[(jq * 5 + 1) * 64 + kp] = acc1;
            sUp[(jq * 5 + 2) * 64 + kp] = acc2;
            sUp[(jq * 5 + 3) * 64 + kp] = acc3;
            sUp[(jq * 5 + 4) * 64 + kp] = acc4;
        }
        __syncthreads();

        // ---- (b) attention scores: warp w owns n in [8w,8w+8), lane = k-quad l
        #pragma unroll
        for (int b = 0; b < 5; ++b) {
            float u0 = 0.f, u1 = 0.f, u2 = 0.f, u3 = 0.f;
            #pragma unroll
            for (int j = 0; j < 4; ++j) {
                float2 pa = up2(sUp[(j * 5 + b) * 64 + 2 * l]);
                float2 pb = up2(sUp[(j * 5 + b) * 64 + 2 * l + 1]);
                u0 += pa.x; u1 += pa.y; u2 += pb.x; u3 += pb.y;
            }
            const uint2* pb_ = prB[b] + l;
            uint2 c = __ldcs(pb_ + (size_t)(w * 8) * 32);
            float v[8];
            #pragma unroll
            for (int i = 0; i < 8; ++i) {
                uint2 nx = __ldcs(pb_ + (size_t)(w * 8 + ((i + 1) & 7)) * 32);
                float2 a01 = __bfloat1622float2(*(const __nv_bfloat162*)&c.x);
                float2 a23 = __bfloat1622float2(*(const __nv_bfloat162*)&c.y);
                float s = tanh_fast(a01.x + u0) * w2v.x;
                s = fmaf(tanh_fast(a01.y + u1), w2v.y, s);
                s = fmaf(tanh_fast(a23.x + u2), w2v.z, s);
                s = fmaf(tanh_fast(a23.y + u3), w2v.w, s);
                v[i] = s;
                c = nx;
            }
            // 8-lane butterfly transpose-reduce, then cross-octet combine
            bool h1 = l & 1, h2 = l & 2, h4 = l & 4;
            float s0 = h1 ? v[0] : v[1];
            float a0 = (h1 ? v[1] : v[0]) + __shfl_xor_sync(0xffffffffu, s0, 1);
            float s1 = h1 ? v[2] : v[3];
            float a1 = (h1 ? v[3] : v[2]) + __shfl_xor_sync(0xffffffffu, s1, 1);
            float s2 = h1 ? v[4] : v[5];
            float a2 = (h1 ? v[5] : v[4]) + __shfl_xor_sync(0xffffffffu, s2, 1);
            float s3 = h1 ? v[6] : v[7];
            float a3 = (h1 ? v[7] : v[6]) + __shfl_xor_sync(0xffffffffu, s3, 1);
            float t0 = h2 ? a0 : a1;
            float bb0 = (h2 ? a1 : a0) + __shfl_xor_sync(0xffffffffu, t0, 2);
            float t1 = h2 ? a2 : a3;
            float bb1 = (h2 ? a3 : a2) + __shfl_xor_sync(0xffffffffu, t1, 2);
            float t2 = h4 ? bb0 : bb1;
            float ev = (h4 ? bb1 : bb0) + __shfl_xor_sync(0xffffffffu, t2, 4);
            ev += __shfl_xor_sync(0xffffffffu, ev, 8);
            ev += __shfl_xor_sync(0xffffffffu, ev, 16);
            if (l < 8) sE[b * 64 + w * 8 + l] = ev + b2;
        }
        __syncthreads();

        // ---- (d1) Whh.h for all 5 batches  +  softmax (warps < cnt)
        ull a0[5], a1[5];
        #pragma unroll
        for (int b = 0; b < 5; ++b) { a0[b] = 0ull; a1[b] = 0ull; }
        if (w < cnt) {
            // softmax for batch w, x_tilde into sXT
            float e0 = sE[w * 64 + l], e1 = sE[w * 64 + l + 32];
            float mx = fmaxf(e0, e1);
            #pragma unroll
            for (int o = 16; o > 0; o >>= 1)
                mx = fmaxf(mx, __shfl_xor_sync(0xffffffffu, mx, o));
            float x0 = __expf(e0 - mx), x1 = __expf(e1 - mx);
            float sm = x0 + x1;
            #pragma unroll
            for (int o = 16; o > 0; o >>= 1)
                sm += __shfl_xor_sync(0xffffffffu, sm, o);
            float inv = 1.0f / sm;
            const float* Xr = X + ((size_t)(b0 + w) * TT + t) * NN;
            sXT[w * 64 + l]      = x0 * inv * Xr[l];
            sXT[w * 64 + l + 32] = x1 * inv * Xr[l + 32];
        }
        {
            ulonglong2 wa = Wh[0], wb = Wh[256];
            #pragma unroll 4
            for (int jb = 0; jb < 32; ++jb) {
                int njp = ((jb + 1) & 31) * 2;
                ulonglong2 wna = Wh[(size_t)njp * 256];
                ulonglong2 wnb = Wh[(size_t)(njp + 1) * 256];
                #pragma unroll
                for (int b = 0; b < 5; ++b) {
                    ulonglong2 hp = *(const ulonglong2*)(hc + b * HCP + jb * 4);
                    fma2(a0[b], hp.x, wa.x);
                    fma2(a1[b], hp.x, wa.y);
                    fma2(a0[b], hp.y, wb.x);
                    fma2(a1[b], hp.y, wb.y);
                }
                wa = wna; wb = wnb;
            }
        }
        __syncthreads();

        // ---- (d2) Wih.x_tilde
        {
            ulonglong2 wa = Wi[0], wb = Wi[256];
            #pragma unroll 4
            for (int nb4 = 0; nb4 < 16; ++nb4) {
                int nnp = ((nb4 + 1) & 15) * 2;
                ulonglong2 wna = Wi[(size_t)nnp * 256];
                ulonglong2 wnb = Wi[(size_t)(nnp + 1) * 256];
                #pragma unroll
                for (int b = 0; b < 5; ++b) {
                    ulonglong2 xp = *(const ulonglong2*)(sXT + b * 64 + nb4 * 4);
                    fma2(a0[b], xp.x, wa.x);
                    fma2(a1[b], xp.x, wa.y);
                    fma2(a0[b], xp.y, wb.x);
                    fma2(a1[b], xp.y, wb.y);
                }
                wa = wna; wb = wnb;
            }
        }

        // ---- (e) horizontal sum + gate exchange + LSTM update
        {
            float s0[5], s1[5], p0[5], p1[5];
            #pragma unroll
            for (int b = 0; b < 5; ++b) {
                float2 r0 = up2(a0[b]), r1 = up2(a1[b]);
                s0[b] = r0.x + r0.y + bj.x;
                s1[b] = r1.x + r1.y + bj.y;
            }
            #pragma unroll
            for (int b = 0; b < 5; ++b) {
                p0[b] = __shfl_xor_sync(0xffffffffu, s0[b], 1);
                p1[b] = __shfl_xor_sync(0xffffffffu, s1[b], 1);
            }
            // gp=0 owns gates (i,f) and batches 0..2; gp=1 owns (g,o), batches 3..4
            #pragma unroll
            for (int b = 0; b < 5; ++b) {
                bool mine = gp ? (b >= 3) : (b < 3);
                if (mine) {
                    float gi = gp ? p0[b] : s0[b];
                    float gf = gp ? p1[b] : s1[b];
                    float gg = gp ? s0[b] : p0[b];
                    float go = gp ? s1[b] : p1[b];
                    float iv = sigmoid_f(gi);
                    float fv = sigmoid_f(gf);
                    float gv = tanhf(gg);
                    float ov = sigmoid_f(go);
                    float cold = hc[b * HCP + 128 + qe];
                    float c2 = fv * cold + iv * gv;
                    float hn = ov * tanhf(c2);
                    hc[b * HCP + qe]       = hn;
                    hc[b * HCP + 128 + qe] = c2;
                    hcdup[qe * 6 + b]         = pk2(hn, hn);
                    hcdup[(128 + qe) * 6 + b] = pk2(c2, c2);
                    if (b < cnt)
                        out[((size_t)(b0 + b) * TT + t) * HH + qe] = hn;
                }
            }
        }
        __syncthreads();
    }
}

// ---------------- launch ------------------------------------------------------
extern "C" void kernel_launch(void* const* d_in, const int* in_sizes, int n_in,
                              void* d_out, int out_size) {
    const float* X       = (const float*)d_in[0];
    const float* W_attn1 = (const float*)d_in[1];
    const float* b_attn1 = (const float*)d_in[2];
    const float* w_attn2 = (const float*)d_in[3];
    const float* b_attn2 = (const float*)d_in[4];
    const float* W_ih    = (const float*)d_in[5];
    const float* W_hh    = (const float*)d_in[6];
    const float* b_ih    = (const float*)d_in[7];
    const float* b_hh    = (const float*)d_in[8];
    float* out = (float*)d_out;

    prep_kernel<<<64, 256>>>(W_attn1, W_ih, W_hh, b_ih, b_hh);
    prex_kernel<<<BB, 256>>>(X, b_attn1);
    dummy_kernel<<<1, 32>>>();   // aligns ncu -s 5 -c 1 onto rnn_kernel
    rnn_kernel<<<GRID, THR, SMEM_FLOATS * sizeof(float)>>>(X, w_attn2, b_attn2, out);
}